// round 1
// baseline (speedup 1.0000x reference)
#include <cuda_runtime.h>
#include <math.h>

// Problem constants: B=4, C=256, H=W=64 -> N=4096, num_heads=1, d=256
#define NB    4
#define NC    256
#define NN    4096
#define NGRP  32

static __device__ float g_xn[NB * NC * NN];
static __device__ float g_q [NB * NC * NN];
static __device__ float g_k [NB * NC * NN];
static __device__ float g_v [NB * NC * NN];
static __device__ float g_o [NB * NC * NN];
static __device__ float g_S [(size_t)NB * NN * NN];   // 256 MB scores

static constexpr size_t STR_CN = (size_t)NC * NN;     // 1048576
static constexpr size_t STR_NN = (size_t)NN * NN;     // 16777216

// ---------------------------------------------------------------------------
// GroupNorm: one block per (batch, group). Group = 8 channels x 4096 spatial.
// ---------------------------------------------------------------------------
__global__ void __launch_bounds__(256) gn_kernel(const float* __restrict__ x,
                                                 const float* __restrict__ w,
                                                 const float* __restrict__ b) {
    int batch = blockIdx.x >> 5;
    int grp   = blockIdx.x & 31;
    const float* xp = x    + ((size_t)batch * NC + grp * 8) * NN;
    float*       op = g_xn + ((size_t)batch * NC + grp * 8) * NN;
    int tid = threadIdx.x;

    float s = 0.f, s2 = 0.f;
    #pragma unroll 4
    for (int i = tid; i < 8192; i += 256) {           // 8192 float4 = 32768 elems
        float4 t = reinterpret_cast<const float4*>(xp)[i];
        s  += t.x + t.y + t.z + t.w;
        s2 += t.x * t.x + t.y * t.y + t.z * t.z + t.w * t.w;
    }
    __shared__ float rs[8], rs2[8];
    __shared__ float sh_mean, sh_rstd;
    int lane = tid & 31, wid = tid >> 5;
    #pragma unroll
    for (int o = 16; o; o >>= 1) {
        s  += __shfl_xor_sync(0xffffffffu, s,  o);
        s2 += __shfl_xor_sync(0xffffffffu, s2, o);
    }
    if (lane == 0) { rs[wid] = s; rs2[wid] = s2; }
    __syncthreads();
    if (tid == 0) {
        float ts = 0.f, ts2 = 0.f;
        #pragma unroll
        for (int i = 0; i < 8; i++) { ts += rs[i]; ts2 += rs2[i]; }
        float mean = ts * (1.0f / 32768.0f);
        float var  = ts2 * (1.0f / 32768.0f) - mean * mean;
        sh_mean = mean;
        sh_rstd = rsqrtf(var + 1e-5f);
    }
    __syncthreads();
    float mean = sh_mean, rstd = sh_rstd;

    #pragma unroll 4
    for (int i = tid; i < 8192; i += 256) {
        int c = grp * 8 + (i >> 10);                  // 1024 float4 per channel
        float sc = rstd * w[c];
        float shf = b[c] - mean * sc;
        float4 t = reinterpret_cast<const float4*>(xp)[i];
        t.x = t.x * sc + shf; t.y = t.y * sc + shf;
        t.z = t.z * sc + shf; t.w = t.w * sc + shf;
        reinterpret_cast<float4*>(op)[i] = t;
    }
}

// ---------------------------------------------------------------------------
// Generic tiled GEMM: C[m][n] = sum_k A(k,m) * B(k,n), BM=128 BN=64 BK=32,
// 256 threads, 8x4 micro-tile. Op selects operands / layouts / epilogue.
// ---------------------------------------------------------------------------
#define OP_QKV  0   // A=qkv_w [768][256] (T), B=g_xn [256][4096]  -> q,k,v (+bias, q*0.0625)
#define OP_S    1   // A=g_q   [256][4096],    B=g_k  [256][4096]  -> g_S
#define OP_AV   2   // A=g_v   [256][4096](T), B=g_S  [4096][4096](T) -> g_o
#define OP_PROJ 3   // A=proj_w[256][256](T),  B=g_o  [256][4096]  -> out (+bias +x)

template <int OP>
__global__ void __launch_bounds__(256) gemm_kernel(const float* __restrict__ extA,
                                                   const float* __restrict__ bias,
                                                   const float* __restrict__ resid,
                                                   float* __restrict__ extOut) {
    constexpr int BM = 128, BN = 64, BK = 32;
    constexpr int K   = (OP == OP_AV) ? 4096 : 256;
    constexpr bool A_T = (OP == OP_QKV || OP == OP_AV || OP == OP_PROJ); // A is [M][K]
    constexpr bool B_T = (OP == OP_AV);                                  // B is [N][K]
    constexpr int LDA = (OP == OP_QKV || OP == OP_PROJ) ? 256 : 4096;
    constexpr int LDB = 4096;

    __shared__ float As[BK][BM + 4];
    __shared__ float Bs[BK][BN + 4];

    size_t bz = blockIdx.z;
    const float* A;
    const float* B;
    if constexpr (OP == OP_QKV)      { A = extA;              B = g_xn + bz * STR_CN; }
    else if constexpr (OP == OP_S)   { A = g_q + bz * STR_CN; B = g_k  + bz * STR_CN; }
    else if constexpr (OP == OP_AV)  { A = g_v + bz * STR_CN; B = g_S  + bz * STR_NN; }
    else                             { A = extA;              B = g_o  + bz * STR_CN; }

    int m0 = blockIdx.y * BM;
    int n0 = blockIdx.x * BN;
    int tid = threadIdx.x;
    int tr = tid >> 4;        // 0..15 : row group (8 rows each)
    int tc = tid & 15;        // 0..15 : col group (4 cols each)

    float acc[8][4];
    #pragma unroll
    for (int i = 0; i < 8; i++)
        #pragma unroll
        for (int j = 0; j < 4; j++) acc[i][j] = 0.f;

    #pragma unroll 1
    for (int k0 = 0; k0 < K; k0 += BK) {
        // ---- load A tile into As[k][m] ----
        if constexpr (A_T) {
            int m = tid >> 3, kq = tid & 7;
            #pragma unroll
            for (int it = 0; it < 4; ++it, m += 32) {
                float4 va = *reinterpret_cast<const float4*>(&A[(size_t)(m0 + m) * LDA + k0 + kq * 4]);
                As[kq * 4 + 0][m] = va.x;
                As[kq * 4 + 1][m] = va.y;
                As[kq * 4 + 2][m] = va.z;
                As[kq * 4 + 3][m] = va.w;
            }
        } else {
            int kk = tid >> 5, m4 = tid & 31;
            #pragma unroll
            for (int it = 0; it < 4; ++it, kk += 8) {
                float4 va = *reinterpret_cast<const float4*>(&A[(size_t)(k0 + kk) * LDA + m0 + m4 * 4]);
                *reinterpret_cast<float4*>(&As[kk][m4 * 4]) = va;
            }
        }
        // ---- load B tile into Bs[k][n] ----
        if constexpr (B_T) {
            int n = tid >> 3, kq = tid & 7;
            #pragma unroll
            for (int it = 0; it < 2; ++it, n += 32) {
                float4 vb = *reinterpret_cast<const float4*>(&B[(size_t)(n0 + n) * LDB + k0 + kq * 4]);
                Bs[kq * 4 + 0][n] = vb.x;
                Bs[kq * 4 + 1][n] = vb.y;
                Bs[kq * 4 + 2][n] = vb.z;
                Bs[kq * 4 + 3][n] = vb.w;
            }
        } else {
            int kk = tid >> 4, n4 = tid & 15;
            #pragma unroll
            for (int it = 0; it < 2; ++it, kk += 16) {
                float4 vb = *reinterpret_cast<const float4*>(&B[(size_t)(k0 + kk) * LDB + n0 + n4 * 4]);
                *reinterpret_cast<float4*>(&Bs[kk][n4 * 4]) = vb;
            }
        }
        __syncthreads();

        #pragma unroll
        for (int kk = 0; kk < BK; ++kk) {
            float4 a0 = *reinterpret_cast<const float4*>(&As[kk][tr * 8]);
            float4 a1 = *reinterpret_cast<const float4*>(&As[kk][tr * 8 + 4]);
            float4 b0 = *reinterpret_cast<const float4*>(&Bs[kk][tc * 4]);
            float av[8] = {a0.x, a0.y, a0.z, a0.w, a1.x, a1.y, a1.z, a1.w};
            float bv[4] = {b0.x, b0.y, b0.z, b0.w};
            #pragma unroll
            for (int i = 0; i < 8; i++)
                #pragma unroll
                for (int j = 0; j < 4; j++)
                    acc[i][j] = fmaf(av[i], bv[j], acc[i][j]);
        }
        __syncthreads();
    }

    // ---- epilogue ----
    int nbase = n0 + tc * 4;
    #pragma unroll
    for (int i = 0; i < 8; i++) {
        int m = m0 + tr * 8 + i;
        float4 r = make_float4(acc[i][0], acc[i][1], acc[i][2], acc[i][3]);
        if constexpr (OP == OP_QKV) {
            float bv = bias[m];
            r.x += bv; r.y += bv; r.z += bv; r.w += bv;
            size_t off = bz * STR_CN + (size_t)(m & 255) * NN + nbase;
            if (m < 256) {
                r.x *= 0.0625f; r.y *= 0.0625f; r.z *= 0.0625f; r.w *= 0.0625f;  // d^-0.5
                *reinterpret_cast<float4*>(&g_q[off]) = r;
            } else if (m < 512) {
                *reinterpret_cast<float4*>(&g_k[off]) = r;
            } else {
                *reinterpret_cast<float4*>(&g_v[off]) = r;
            }
        } else if constexpr (OP == OP_S) {
            *reinterpret_cast<float4*>(&g_S[bz * STR_NN + (size_t)m * NN + nbase]) = r;
        } else if constexpr (OP == OP_AV) {
            *reinterpret_cast<float4*>(&g_o[bz * STR_CN + (size_t)m * NN + nbase]) = r;
        } else {  // OP_PROJ: + bias + residual x
            float bv = bias[m];
            size_t off = bz * STR_CN + (size_t)m * NN + nbase;
            float4 xr = *reinterpret_cast<const float4*>(&resid[off]);
            r.x += bv + xr.x; r.y += bv + xr.y; r.z += bv + xr.z; r.w += bv + xr.w;
            *reinterpret_cast<float4*>(&extOut[off]) = r;
        }
    }
}

// ---------------------------------------------------------------------------
// Row softmax over g_S: one block per row (4*4096 rows of 4096).
// ---------------------------------------------------------------------------
__global__ void __launch_bounds__(256) softmax_kernel() {
    size_t row = blockIdx.x;
    float* p = g_S + row * NN;
    int tid = threadIdx.x;
    int lane = tid & 31, wid = tid >> 5;
    __shared__ float red[8];
    __shared__ float sh_bcast;

    float4 v[4];
    float mx = -INFINITY;
    #pragma unroll
    for (int i = 0; i < 4; i++) {
        v[i] = reinterpret_cast<float4*>(p)[tid + i * 256];
        mx = fmaxf(mx, fmaxf(fmaxf(v[i].x, v[i].y), fmaxf(v[i].z, v[i].w)));
    }
    #pragma unroll
    for (int o = 16; o; o >>= 1) mx = fmaxf(mx, __shfl_xor_sync(0xffffffffu, mx, o));
    if (lane == 0) red[wid] = mx;
    __syncthreads();
    if (tid == 0) {
        float m = red[0];
        #pragma unroll
        for (int i = 1; i < 8; i++) m = fmaxf(m, red[i]);
        sh_bcast = m;
    }
    __syncthreads();
    mx = sh_bcast;
    __syncthreads();

    float sum = 0.f;
    #pragma unroll
    for (int i = 0; i < 4; i++) {
        v[i].x = __expf(v[i].x - mx); v[i].y = __expf(v[i].y - mx);
        v[i].z = __expf(v[i].z - mx); v[i].w = __expf(v[i].w - mx);
        sum += v[i].x + v[i].y + v[i].z + v[i].w;
    }
    #pragma unroll
    for (int o = 16; o; o >>= 1) sum += __shfl_xor_sync(0xffffffffu, sum, o);
    if (lane == 0) red[wid] = sum;
    __syncthreads();
    if (tid == 0) {
        float s = 0.f;
        #pragma unroll
        for (int i = 0; i < 8; i++) s += red[i];
        sh_bcast = 1.0f / s;
    }
    __syncthreads();
    float inv = sh_bcast;

    #pragma unroll
    for (int i = 0; i < 4; i++) {
        v[i].x *= inv; v[i].y *= inv; v[i].z *= inv; v[i].w *= inv;
        reinterpret_cast<float4*>(p)[tid + i * 256] = v[i];
    }
}

// ---------------------------------------------------------------------------
extern "C" void kernel_launch(void* const* d_in, const int* in_sizes, int n_in,
                              void* d_out, int out_size) {
    const float* x      = (const float*)d_in[0];
    const float* norm_w = (const float*)d_in[1];
    const float* norm_b = (const float*)d_in[2];
    const float* qkv_w  = (const float*)d_in[3];
    const float* qkv_b  = (const float*)d_in[4];
    const float* proj_w = (const float*)d_in[5];
    const float* proj_b = (const float*)d_in[6];
    float* out = (float*)d_out;

    // 1. GroupNorm -> g_xn
    gn_kernel<<<NB * NGRP, 256>>>(x, norm_w, norm_b);

    // 2. QKV GEMM: [768,256] x [256,4096] per batch -> g_q (scaled), g_k, g_v
    gemm_kernel<OP_QKV><<<dim3(NN / 64, 768 / 128, NB), 256>>>(qkv_w, qkv_b, nullptr, nullptr);

    // 3. S = Q^T K  (K-dim = 256) -> g_S
    gemm_kernel<OP_S><<<dim3(NN / 64, NN / 128, NB), 256>>>(nullptr, nullptr, nullptr, nullptr);

    // 4. softmax rows of g_S
    softmax_kernel<<<NB * NN, 256>>>();

    // 5. O = V P^T (K-dim = 4096) -> g_o
    gemm_kernel<OP_AV><<<dim3(NN / 64, NC / 128, NB), 256>>>(nullptr, nullptr, nullptr, nullptr);

    // 6. proj + bias + residual -> out
    gemm_kernel<OP_PROJ><<<dim3(NN / 64, NC / 128, NB), 256>>>(proj_w, proj_b, x, out);
}